// round 15
// baseline (speedup 1.0000x reference)
#include <cuda_runtime.h>
#include <cuda_fp16.h>
#include <cstdint>

#define TPB 224

namespace {
constexpr int Cn = 64, Hn = 112, Wn = 112, Fn = 128;
constexpr int PIX   = Hn * Wn;           // 12544
constexpr int MT    = 224;               // pixels per CTA = exactly 2 image rows
constexpr int CPW   = 484;               // words per channel-pair (4 rows x 120 + pad)
constexpr int ROWW  = 120;
constexpr int SIN_W = 32 * CPW;          // 15488 words
constexpr int BTAP  = 4096;              // B words per tap: 4s * 8chunk * 32lane * 4
constexpr int SMEM_WORDS = SIN_W + 9 * BTAP;  // 52352
constexpr int SMEM_BYTES = SMEM_WORDS * 4;    // 209408 (1 CTA/SM)
}

// chunk-major fp16 B fragments: [tap][s][c(8)][lane(32)][4]
__device__ __align__(16) uint32_t g_wt[9 * BTAP];

__device__ __forceinline__ uint32_t smem_u32(const void* p) {
    uint32_t a;
    asm("{ .reg .u64 t; cvta.to.shared.u64 t, %1; cvt.u32.u64 %0, t; }" : "=r"(a) : "l"(p));
    return a;
}
__device__ __forceinline__ void cpa16(uint32_t dst, const void* src) {
    asm volatile("cp.async.cg.shared.global [%0], [%1], 16;"
                 :: "r"(dst), "l"(src));
}
#define CP_COMMIT() asm volatile("cp.async.commit_group;" ::: "memory")
#define CP_WAIT0()  asm volatile("cp.async.wait_group 0;"  ::: "memory")

// word i -> (tap, s, c, lane, w):  ni = 2c + (w>>1), which = w&1
__global__ void pack_wt_h_kernel(const float* __restrict__ wt) {
    int i = blockIdx.x * 256 + threadIdx.x;
    if (i >= 9 * BTAP) return;
    int w    = i & 3;
    int lane = (i >> 2) & 31;
    int c    = (i >> 7) & 7;
    int s    = (i >> 10) & 3;
    int tap  = i >> 12;
    int ni    = 2 * c + (w >> 1);
    int which = w & 1;
    int f  = ni * 8 + (lane >> 2);
    int c0 = s * 16 + which * 8 + 2 * (lane & 3);
    float v0 = wt[f * 576 + c0 * 9 + tap];
    float v1 = wt[f * 576 + (c0 + 1) * 9 + tap];
    __half2 h = __floats2half2_rn(v0, v1);   // low = even k
    g_wt[i] = *(uint32_t*)&h;
}

// D[m=224 pixels][n=128 filters]; 7 warps, warp tile 32x128; all-tap-resident B
__global__ void __launch_bounds__(TPB, 1)
conv_hmma3_kernel(const float* __restrict__ in, float* __restrict__ out)
{
    extern __shared__ uint32_t smem[];
    const uint32_t sbase = smem_u32(smem);

    const int tid  = threadIdx.x;
    const int lane = tid & 31;
    const int wid  = tid >> 5;           // 0..6
    const int bb   = blockIdx.y;
    const int p0   = blockIdx.x * MT;    // multiple of 224 -> px0 == 0
    const int py0  = p0 / Wn;            // = 2*blockIdx.x

    const int wm0 = wid * 32;            // warp's 32-pixel m origin
    const float* in_b = in + (size_t)bb * Cn * PIX;

    // per-thread A fragment offsets: 4 m-values -> word offset (r*120 + x + 3)
    int om[4];
#pragma unroll
    for (int q = 0; q < 4; ++q) {
        int m = wm0 + (lane >> 2) + (q >> 1) * 16 + (q & 1) * 8;
        int x = m, r = 0;
        if (x >= Wn) { x -= Wn; r = 1; }
        om[q] = r * ROWW + x + 3;
    }

    // zero the x-border words (cols 3 and 116), all cp, all rows: 256 words
    for (int e = tid; e < 256; e += TPB) {
        int cp = e >> 3, ry = (e >> 1) & 3, side = e & 1;
        smem[cp * CPW + ry * ROWW + (side ? 116 : 3)] = 0;
    }

    float acc[2][16][4];
#pragma unroll
    for (int mi = 0; mi < 2; ++mi)
#pragma unroll
        for (int ni = 0; ni < 16; ++ni)
#pragma unroll
            for (int c = 0; c < 4; ++c) acc[mi][ni][c] = 0.f;

    // ---- stage B for ALL 9 taps via cp.async (overlaps input LDG below) ----
    {
        const uint4* wb = (const uint4*)g_wt;
#pragma unroll
        for (int i = 0; i < 42; ++i) {       // 9216 uint4 / 224 threads
            int e = i * TPB + tid;
            if (e < 9 * BTAP / 4)
                cpa16(sbase + (SIN_W + e * 4) * 4, wb + e);
        }
        CP_COMMIT();
    }

    // ---- stage input once: 64 channels as half2 channel pairs, 4 rows ----
    {
#pragma unroll
        for (int i = 0; i < 16; ++i) {       // 3584 units / 224 threads
            int e   = i * TPB + tid;
            int x4  = e % 28;
            int t   = e / 28;                // 0..127
            int ry  = t & 3;
            int cp  = t >> 2;                // 0..31
            int y   = py0 - 1 + ry;
            float4 fa, fb;
            if ((unsigned)y < (unsigned)Hn) {
                const float* base = in_b + (size_t)(2 * cp) * PIX + y * Wn + x4 * 4;
                fa = *(const float4*)base;
                fb = *(const float4*)(base + PIX);
            } else {
                fa = make_float4(0.f, 0.f, 0.f, 0.f);
                fb = fa;
            }
            __half2 h0 = __floats2half2_rn(fa.x, fb.x);
            __half2 h1 = __floats2half2_rn(fa.y, fb.y);
            __half2 h2 = __floats2half2_rn(fa.z, fb.z);
            __half2 h3 = __floats2half2_rn(fa.w, fb.w);
            uint4 v = make_uint4(*(uint32_t*)&h0, *(uint32_t*)&h1,
                                 *(uint32_t*)&h2, *(uint32_t*)&h3);
            *(uint4*)&smem[cp * CPW + ry * ROWW + 4 + x4 * 4] = v;
        }
    }

    CP_WAIT0();
    __syncthreads();          // input STS + B cp.async visible to all

    // ---- barrier-free mainloop: 9 taps x 4 k16-steps, 32 MMAs each ----
#pragma unroll 1
    for (int tap = 0; tap < 9; ++tap) {
        const int dy = tap / 3, dx = tap - dy * 3;
        const int dyx = dy * ROWW + dx;
        const uint32_t* sB = smem + SIN_W + tap * BTAP;

#pragma unroll
        for (int s = 0; s < 4; ++s) {
            // B: 8 conflict-free LDS.128 (chunk-major: lanes stride 16B)
            const uint32_t* pb = sB + s * 1024 + lane * 4;
            uint4 q[8];
#pragma unroll
            for (int c = 0; c < 8; ++c)
                q[c] = *(const uint4*)(pb + c * 128);

            // A: 8 LDS.32
            const uint32_t* pa  = smem + (s * 8 + (lane & 3)) * CPW + dyx;
            const uint32_t* pa4 = pa + 4 * CPW;
            uint32_t af[2][4];
#pragma unroll
            for (int mi = 0; mi < 2; ++mi) {
                af[mi][0] = pa [om[2 * mi]];
                af[mi][1] = pa [om[2 * mi + 1]];
                af[mi][2] = pa4[om[2 * mi]];
                af[mi][3] = pa4[om[2 * mi + 1]];
            }
#pragma unroll
            for (int mi = 0; mi < 2; ++mi)
#pragma unroll
                for (int ni = 0; ni < 16; ++ni) {
                    const uint32_t b0 = (ni & 1) ? q[ni >> 1].z : q[ni >> 1].x;
                    const uint32_t b1 = (ni & 1) ? q[ni >> 1].w : q[ni >> 1].y;
                    asm volatile(
                        "mma.sync.aligned.m16n8k16.row.col.f32.f16.f16.f32 "
                        "{%0,%1,%2,%3}, {%4,%5,%6,%7}, {%8,%9}, {%0,%1,%2,%3};"
                        : "+f"(acc[mi][ni][0]), "+f"(acc[mi][ni][1]),
                          "+f"(acc[mi][ni][2]), "+f"(acc[mi][ni][3])
                        : "r"(af[mi][0]), "r"(af[mi][1]),
                          "r"(af[mi][2]), "r"(af[mi][3]),
                          "r"(b0), "r"(b1));
                }
        }
    }

    // ---- coalesced epilogue: acc -> smem transpose -> contiguous STG ----
    float* sf = (float*)smem;            // s_out[224][68] = 59.5KB (reuses s_in)
    float* out_b = out + (size_t)bb * Fn * PIX + p0;
#pragma unroll 1
    for (int pass = 0; pass < 2; ++pass) {
        __syncthreads();                 // mainloop done / previous pass consumed
#pragma unroll
        for (int mi = 0; mi < 2; ++mi) {
            int r0 = wm0 + mi * 16 + (lane >> 2);
#pragma unroll
            for (int nj = 0; nj < 8; ++nj) {
                int ni = pass * 8 + nj;
                int nn = nj * 8 + (lane & 3) * 2;
                *(float2*)&sf[r0 * 68 + nn] =
                    make_float2(acc[mi][ni][0], acc[mi][ni][1]);
                *(float2*)&sf[(r0 + 8) * 68 + nn] =
                    make_float2(acc[mi][ni][2], acc[mi][ni][3]);
            }
        }
        __syncthreads();
        // thread tid owns pixel m=tid; 16 LDS.128 (conflict-free), 64 coalesced STG
#pragma unroll
        for (int jj = 0; jj < 16; ++jj) {
            float4 v = *(const float4*)&sf[tid * 68 + jj * 4];
            float* dst = out_b + (size_t)(pass * 64 + jj * 4) * PIX + tid;
            dst[0]               = v.x;
            dst[(size_t)PIX]     = v.y;
            dst[(size_t)2 * PIX] = v.z;
            dst[(size_t)3 * PIX] = v.w;
        }
    }
}

extern "C" void kernel_launch(void* const* d_in, const int* in_sizes, int n_in,
                              void* d_out, int out_size)
{
    (void)in_sizes; (void)n_in; (void)out_size;
    const float* in = (const float*)d_in[0];   // [32,64,112,112]
    const float* wt = (const float*)d_in[1];   // [128,64,3,3]
    float* out = (float*)d_out;                // [32,128,112,112]

    static bool attr_set = false;
    if (!attr_set) {
        cudaFuncSetAttribute(conv_hmma3_kernel,
                             cudaFuncAttributeMaxDynamicSharedMemorySize, SMEM_BYTES);
        attr_set = true;
    }
    pack_wt_h_kernel<<<(9 * BTAP + 255) / 256, 256>>>(wt);
    dim3 grid(PIX / MT, 32);                   // (56, 32) = 1792 CTAs
    conv_hmma3_kernel<<<grid, TPB, SMEM_BYTES>>>(in, out);
}

// round 16
// speedup vs baseline: 1.0041x; 1.0041x over previous
#include <cuda_runtime.h>
#include <cuda_fp16.h>
#include <cstdint>

#define TPB 224

namespace {
constexpr int Cn = 64, Hn = 112, Wn = 112, Fn = 128;
constexpr int PIX   = Hn * Wn;           // 12544
constexpr int MT    = 224;               // pixels per CTA = exactly 2 image rows
constexpr int CPW   = 484;               // words per channel-pair (4 rows x 120 + pad)
constexpr int ROWW  = 120;
constexpr int SIN_W = 32 * CPW;          // 15488 words
constexpr int BTAP  = 4096;              // B words per tap: 4s * 8chunk * 32lane * 4
constexpr int SMEM_WORDS = SIN_W + 9 * BTAP;  // 52352
constexpr int SMEM_BYTES = SMEM_WORDS * 4;    // 209408 (1 CTA/SM)
}

// chunk-major fp16 B fragments: [tap][s][c(8)][lane(32)][4]
__device__ __align__(16) uint32_t g_wt[9 * BTAP];

__device__ __forceinline__ uint32_t smem_u32(const void* p) {
    uint32_t a;
    asm("{ .reg .u64 t; cvta.to.shared.u64 t, %1; cvt.u32.u64 %0, t; }" : "=r"(a) : "l"(p));
    return a;
}
__device__ __forceinline__ void cpa16(uint32_t dst, const void* src) {
    asm volatile("cp.async.cg.shared.global [%0], [%1], 16;"
                 :: "r"(dst), "l"(src));
}
#define CP_COMMIT() asm volatile("cp.async.commit_group;" ::: "memory")
#define CP_WAIT0()  asm volatile("cp.async.wait_group 0;"  ::: "memory")

// word i -> (tap, s, c, lane, w):  ni = 2c + (w>>1), which = w&1
__global__ void pack_wt_h_kernel(const float* __restrict__ wt) {
    int i = blockIdx.x * 256 + threadIdx.x;
    if (i >= 9 * BTAP) return;
    int w    = i & 3;
    int lane = (i >> 2) & 31;
    int c    = (i >> 7) & 7;
    int s    = (i >> 10) & 3;
    int tap  = i >> 12;
    int ni    = 2 * c + (w >> 1);
    int which = w & 1;
    int f  = ni * 8 + (lane >> 2);
    int c0 = s * 16 + which * 8 + 2 * (lane & 3);
    float v0 = wt[f * 576 + c0 * 9 + tap];
    float v1 = wt[f * 576 + (c0 + 1) * 9 + tap];
    __half2 h = __floats2half2_rn(v0, v1);   // low = even k
    g_wt[i] = *(uint32_t*)&h;
}

// D[m=224 pixels][n=128 filters]; 7 warps, warp tile 32x128; all-tap-resident B.
// B live range is ONE uint4 at a time (load chunk -> 4 MMAs -> dead) to stay
// under the register cap (R15 spilled with the whole 32-reg B block live).
__global__ void __launch_bounds__(TPB, 1)
conv_hmma4_kernel(const float* __restrict__ in, float* __restrict__ out)
{
    extern __shared__ uint32_t smem[];
    const uint32_t sbase = smem_u32(smem);

    const int tid  = threadIdx.x;
    const int lane = tid & 31;
    const int wid  = tid >> 5;           // 0..6
    const int bb   = blockIdx.y;
    const int p0   = blockIdx.x * MT;    // multiple of 224 -> px0 == 0
    const int py0  = p0 / Wn;            // = 2*blockIdx.x

    const int wm0 = wid * 32;            // warp's 32-pixel m origin
    const float* in_b = in + (size_t)bb * Cn * PIX;

    // per-thread A fragment offsets: 4 m-values -> word offset (r*120 + x + 3)
    int om[4];
#pragma unroll
    for (int q = 0; q < 4; ++q) {
        int m = wm0 + (lane >> 2) + (q >> 1) * 16 + (q & 1) * 8;
        int x = m, r = 0;
        if (x >= Wn) { x -= Wn; r = 1; }
        om[q] = r * ROWW + x + 3;
    }

    // zero the x-border words (cols 3 and 116), all cp, all rows: 256 words
    for (int e = tid; e < 256; e += TPB) {
        int cp = e >> 3, ry = (e >> 1) & 3, side = e & 1;
        smem[cp * CPW + ry * ROWW + (side ? 116 : 3)] = 0;
    }

    float acc[2][16][4];
#pragma unroll
    for (int mi = 0; mi < 2; ++mi)
#pragma unroll
        for (int ni = 0; ni < 16; ++ni)
#pragma unroll
            for (int c = 0; c < 4; ++c) acc[mi][ni][c] = 0.f;

    // ---- stage B for ALL 9 taps via cp.async (overlaps input LDG below) ----
    {
        const uint4* wb = (const uint4*)g_wt;
#pragma unroll
        for (int i = 0; i < 42; ++i) {       // 9216 uint4 / 224 threads
            int e = i * TPB + tid;
            if (e < 9 * BTAP / 4)
                cpa16(sbase + (SIN_W + e * 4) * 4, wb + e);
        }
        CP_COMMIT();
    }

    // ---- stage input once: 64 channels as half2 channel pairs, 4 rows ----
    {
#pragma unroll
        for (int i = 0; i < 16; ++i) {       // 3584 units / 224 threads
            int e   = i * TPB + tid;
            int x4  = e % 28;
            int t   = e / 28;                // 0..127
            int ry  = t & 3;
            int cp  = t >> 2;                // 0..31
            int y   = py0 - 1 + ry;
            float4 fa, fb;
            if ((unsigned)y < (unsigned)Hn) {
                const float* base = in_b + (size_t)(2 * cp) * PIX + y * Wn + x4 * 4;
                fa = *(const float4*)base;
                fb = *(const float4*)(base + PIX);
            } else {
                fa = make_float4(0.f, 0.f, 0.f, 0.f);
                fb = fa;
            }
            __half2 h0 = __floats2half2_rn(fa.x, fb.x);
            __half2 h1 = __floats2half2_rn(fa.y, fb.y);
            __half2 h2 = __floats2half2_rn(fa.z, fb.z);
            __half2 h3 = __floats2half2_rn(fa.w, fb.w);
            uint4 v = make_uint4(*(uint32_t*)&h0, *(uint32_t*)&h1,
                                 *(uint32_t*)&h2, *(uint32_t*)&h3);
            *(uint4*)&smem[cp * CPW + ry * ROWW + 4 + x4 * 4] = v;
        }
    }

    CP_WAIT0();
    __syncthreads();          // input STS + B cp.async visible to all

    // ---- barrier-free mainloop: 9 taps x 4 k16-steps ----
#pragma unroll 1
    for (int tap = 0; tap < 9; ++tap) {
        const int dy = tap / 3, dx = tap - dy * 3;
        const int dyx = dy * ROWW + dx;
        const uint32_t* sB = smem + SIN_W + tap * BTAP;

#pragma unroll
        for (int s = 0; s < 4; ++s) {
            // A: 8 LDS.32
            const uint32_t* pa  = smem + (s * 8 + (lane & 3)) * CPW + dyx;
            const uint32_t* pa4 = pa + 4 * CPW;
            uint32_t af[2][4];
#pragma unroll
            for (int mi = 0; mi < 2; ++mi) {
                af[mi][0] = pa [om[2 * mi]];
                af[mi][1] = pa [om[2 * mi + 1]];
                af[mi][2] = pa4[om[2 * mi]];
                af[mi][3] = pa4[om[2 * mi + 1]];
            }
            // B: 8 chunks; each chunk is ONE LDS.128 followed by its 4 MMAs
            const uint32_t* pb = sB + s * 1024 + lane * 4;
#pragma unroll
            for (int c = 0; c < 8; ++c) {
                const uint4 q = *(const uint4*)(pb + c * 128);
#pragma unroll
                for (int mi = 0; mi < 2; ++mi) {
                    asm volatile(
                        "mma.sync.aligned.m16n8k16.row.col.f32.f16.f16.f32 "
                        "{%0,%1,%2,%3}, {%4,%5,%6,%7}, {%8,%9}, {%0,%1,%2,%3};"
                        : "+f"(acc[mi][2 * c][0]), "+f"(acc[mi][2 * c][1]),
                          "+f"(acc[mi][2 * c][2]), "+f"(acc[mi][2 * c][3])
                        : "r"(af[mi][0]), "r"(af[mi][1]),
                          "r"(af[mi][2]), "r"(af[mi][3]),
                          "r"(q.x), "r"(q.y));
                    asm volatile(
                        "mma.sync.aligned.m16n8k16.row.col.f32.f16.f16.f32 "
                        "{%0,%1,%2,%3}, {%4,%5,%6,%7}, {%8,%9}, {%0,%1,%2,%3};"
                        : "+f"(acc[mi][2 * c + 1][0]), "+f"(acc[mi][2 * c + 1][1]),
                          "+f"(acc[mi][2 * c + 1][2]), "+f"(acc[mi][2 * c + 1][3])
                        : "r"(af[mi][0]), "r"(af[mi][1]),
                          "r"(af[mi][2]), "r"(af[mi][3]),
                          "r"(q.z), "r"(q.w));
                }
            }
        }
    }

    // ---- coalesced epilogue: acc -> smem transpose -> contiguous STG ----
    float* sf = (float*)smem;            // s_out[224][68] = 59.5KB (reuses s_in)
    float* out_b = out + (size_t)bb * Fn * PIX + p0;
#pragma unroll 1
    for (int pass = 0; pass < 2; ++pass) {
        __syncthreads();                 // mainloop done / previous pass consumed
#pragma unroll
        for (int mi = 0; mi < 2; ++mi) {
            int r0 = wm0 + mi * 16 + (lane >> 2);
#pragma unroll
            for (int nj = 0; nj < 8; ++nj) {
                int ni = pass * 8 + nj;
                int nn = nj * 8 + (lane & 3) * 2;
                *(float2*)&sf[r0 * 68 + nn] =
                    make_float2(acc[mi][ni][0], acc[mi][ni][1]);
                *(float2*)&sf[(r0 + 8) * 68 + nn] =
                    make_float2(acc[mi][ni][2], acc[mi][ni][3]);
            }
        }
        __syncthreads();
        // thread tid owns pixel m=tid; 16 LDS.128 (conflict-free), 64 coalesced STG
#pragma unroll
        for (int jj = 0; jj < 16; ++jj) {
            float4 v = *(const float4*)&sf[tid * 68 + jj * 4];
            float* dst = out_b + (size_t)(pass * 64 + jj * 4) * PIX + tid;
            dst[0]               = v.x;
            dst[(size_t)PIX]     = v.y;
            dst[(size_t)2 * PIX] = v.z;
            dst[(size_t)3 * PIX] = v.w;
        }
    }
}

extern "C" void kernel_launch(void* const* d_in, const int* in_sizes, int n_in,
                              void* d_out, int out_size)
{
    (void)in_sizes; (void)n_in; (void)out_size;
    const float* in = (const float*)d_in[0];   // [32,64,112,112]
    const float* wt = (const float*)d_in[1];   // [128,64,3,3]
    float* out = (float*)d_out;                // [32,128,112,112]

    static bool attr_set = false;
    if (!attr_set) {
        cudaFuncSetAttribute(conv_hmma4_kernel,
                             cudaFuncAttributeMaxDynamicSharedMemorySize, SMEM_BYTES);
        attr_set = true;
    }
    pack_wt_h_kernel<<<(9 * BTAP + 255) / 256, 256>>>(wt);
    dim3 grid(PIX / MT, 32);                   // (56, 32) = 1792 CTAs
    conv_hmma4_kernel<<<grid, TPB, SMEM_BYTES>>>(in, out);
}

// round 17
// speedup vs baseline: 4.8637x; 4.8437x over previous
#include <cuda_runtime.h>
#include <cuda_fp16.h>
#include <cstdint>

#define TPB 224

namespace {
constexpr int Cn = 64, Hn = 112, Wn = 112, Fn = 128;
constexpr int PIX   = Hn * Wn;           // 12544
constexpr int MT    = 224;               // pixels per CTA = exactly 2 image rows
constexpr int CPW   = 484;               // words per channel-pair (4 rows x 120 + pad)
constexpr int ROWW  = 120;
constexpr int SIN_W = 32 * CPW;          // 15488 words
constexpr int BTAP  = 4096;              // B words per tap: 4s * 8chunk * 32lane * 4
constexpr int SMEM_WORDS = SIN_W + 9 * BTAP;  // 52352
constexpr int SMEM_BYTES = SMEM_WORDS * 4;    // 209408 (1 CTA/SM)
}

// chunk-major fp16 B fragments: [tap][s][c(8)][lane(32)][4]
__device__ __align__(16) uint32_t g_wt[9 * BTAP];

__device__ __forceinline__ uint32_t smem_u32(const void* p) {
    uint32_t a;
    asm("{ .reg .u64 t; cvta.to.shared.u64 t, %1; cvt.u32.u64 %0, t; }" : "=r"(a) : "l"(p));
    return a;
}
__device__ __forceinline__ void cpa16(uint32_t dst, const void* src) {
    asm volatile("cp.async.cg.shared.global [%0], [%1], 16;"
                 :: "r"(dst), "l"(src));
}
#define CP_COMMIT() asm volatile("cp.async.commit_group;" ::: "memory")
#define CP_WAIT0()  asm volatile("cp.async.wait_group 0;"  ::: "memory")

// word i -> (tap, s, c, lane, w):  ni = 2c + (w>>1), which = w&1
__global__ void pack_wt_h_kernel(const float* __restrict__ wt) {
    int i = blockIdx.x * 256 + threadIdx.x;
    if (i >= 9 * BTAP) return;
    int w    = i & 3;
    int lane = (i >> 2) & 31;
    int c    = (i >> 7) & 7;
    int s    = (i >> 10) & 3;
    int tap  = i >> 12;
    int ni    = 2 * c + (w >> 1);
    int which = w & 1;
    int f  = ni * 8 + (lane >> 2);
    int c0 = s * 16 + which * 8 + 2 * (lane & 3);
    float v0 = wt[f * 576 + c0 * 9 + tap];
    float v1 = wt[f * 576 + (c0 + 1) * 9 + tap];
    __half2 h = __floats2half2_rn(v0, v1);   // low = even k
    g_wt[i] = *(uint32_t*)&h;
}

// D[m=224 pixels][n=128 filters]; 7 warps, warp tile 32x128; all-tap-resident B.
// Epilogue fully unrolled: acc indices must ALL be compile-time, otherwise
// ptxas demotes acc to local memory (the R15/R16 disaster).
__global__ void __launch_bounds__(TPB, 1)
conv_hmma5_kernel(const float* __restrict__ in, float* __restrict__ out)
{
    extern __shared__ uint32_t smem[];
    const uint32_t sbase = smem_u32(smem);

    const int tid  = threadIdx.x;
    const int lane = tid & 31;
    const int wid  = tid >> 5;           // 0..6
    const int bb   = blockIdx.y;
    const int p0   = blockIdx.x * MT;    // multiple of 224 -> px0 == 0
    const int py0  = p0 / Wn;            // = 2*blockIdx.x

    const int wm0 = wid * 32;            // warp's 32-pixel m origin
    const float* in_b = in + (size_t)bb * Cn * PIX;

    // per-thread A fragment offsets: 4 m-values -> word offset (r*120 + x + 3)
    int om[4];
#pragma unroll
    for (int q = 0; q < 4; ++q) {
        int m = wm0 + (lane >> 2) + (q >> 1) * 16 + (q & 1) * 8;
        int x = m, r = 0;
        if (x >= Wn) { x -= Wn; r = 1; }
        om[q] = r * ROWW + x + 3;
    }

    // zero the x-border words (cols 3 and 116), all cp, all rows: 256 words
    for (int e = tid; e < 256; e += TPB) {
        int cp = e >> 3, ry = (e >> 1) & 3, side = e & 1;
        smem[cp * CPW + ry * ROWW + (side ? 116 : 3)] = 0;
    }

    float acc[2][16][4];
#pragma unroll
    for (int mi = 0; mi < 2; ++mi)
#pragma unroll
        for (int ni = 0; ni < 16; ++ni)
#pragma unroll
            for (int c = 0; c < 4; ++c) acc[mi][ni][c] = 0.f;

    // ---- stage B for ALL 9 taps via cp.async (overlaps input LDG below) ----
    {
        const uint4* wb = (const uint4*)g_wt;
#pragma unroll
        for (int i = 0; i < 42; ++i) {       // 9216 uint4 / 224 threads
            int e = i * TPB + tid;
            if (e < 9 * BTAP / 4)
                cpa16(sbase + (SIN_W + e * 4) * 4, wb + e);
        }
        CP_COMMIT();
    }

    // ---- stage input once: 64 channels as half2 channel pairs, 4 rows ----
    {
#pragma unroll
        for (int i = 0; i < 16; ++i) {       // 3584 units / 224 threads
            int e   = i * TPB + tid;
            int x4  = e % 28;
            int t   = e / 28;                // 0..127
            int ry  = t & 3;
            int cp  = t >> 2;                // 0..31
            int y   = py0 - 1 + ry;
            float4 fa, fb;
            if ((unsigned)y < (unsigned)Hn) {
                const float* base = in_b + (size_t)(2 * cp) * PIX + y * Wn + x4 * 4;
                fa = *(const float4*)base;
                fb = *(const float4*)(base + PIX);
            } else {
                fa = make_float4(0.f, 0.f, 0.f, 0.f);
                fb = fa;
            }
            __half2 h0 = __floats2half2_rn(fa.x, fb.x);
            __half2 h1 = __floats2half2_rn(fa.y, fb.y);
            __half2 h2 = __floats2half2_rn(fa.z, fb.z);
            __half2 h3 = __floats2half2_rn(fa.w, fb.w);
            uint4 v = make_uint4(*(uint32_t*)&h0, *(uint32_t*)&h1,
                                 *(uint32_t*)&h2, *(uint32_t*)&h3);
            *(uint4*)&smem[cp * CPW + ry * ROWW + 4 + x4 * 4] = v;
        }
    }

    CP_WAIT0();
    __syncthreads();          // input STS + B cp.async visible to all

    // ---- barrier-free mainloop: 9 taps x 4 k16-steps ----
#pragma unroll 1
    for (int tap = 0; tap < 9; ++tap) {
        const int dy = tap / 3, dx = tap - dy * 3;
        const int dyx = dy * ROWW + dx;
        const uint32_t* sB = smem + SIN_W + tap * BTAP;

#pragma unroll
        for (int s = 0; s < 4; ++s) {
            // A: 8 LDS.32
            const uint32_t* pa  = smem + (s * 8 + (lane & 3)) * CPW + dyx;
            const uint32_t* pa4 = pa + 4 * CPW;
            uint32_t af[2][4];
#pragma unroll
            for (int mi = 0; mi < 2; ++mi) {
                af[mi][0] = pa [om[2 * mi]];
                af[mi][1] = pa [om[2 * mi + 1]];
                af[mi][2] = pa4[om[2 * mi]];
                af[mi][3] = pa4[om[2 * mi + 1]];
            }
            // B: 8 chunks; each chunk is ONE LDS.128 followed by its 4 MMAs
            const uint32_t* pb = sB + s * 1024 + lane * 4;
#pragma unroll
            for (int c = 0; c < 8; ++c) {
                const uint4 q = *(const uint4*)(pb + c * 128);
#pragma unroll
                for (int mi = 0; mi < 2; ++mi) {
                    asm volatile(
                        "mma.sync.aligned.m16n8k16.row.col.f32.f16.f16.f32 "
                        "{%0,%1,%2,%3}, {%4,%5,%6,%7}, {%8,%9}, {%0,%1,%2,%3};"
                        : "+f"(acc[mi][2 * c][0]), "+f"(acc[mi][2 * c][1]),
                          "+f"(acc[mi][2 * c][2]), "+f"(acc[mi][2 * c][3])
                        : "r"(af[mi][0]), "r"(af[mi][1]),
                          "r"(af[mi][2]), "r"(af[mi][3]),
                          "r"(q.x), "r"(q.y));
                    asm volatile(
                        "mma.sync.aligned.m16n8k16.row.col.f32.f16.f16.f32 "
                        "{%0,%1,%2,%3}, {%4,%5,%6,%7}, {%8,%9}, {%0,%1,%2,%3};"
                        : "+f"(acc[mi][2 * c + 1][0]), "+f"(acc[mi][2 * c + 1][1]),
                          "+f"(acc[mi][2 * c + 1][2]), "+f"(acc[mi][2 * c + 1][3])
                        : "r"(af[mi][0]), "r"(af[mi][1]),
                          "r"(af[mi][2]), "r"(af[mi][3]),
                          "r"(q.z), "r"(q.w));
                }
            }
        }
    }

    // ---- coalesced epilogue: FULLY UNROLLED (compile-time acc indices) ----
    float* sf = (float*)smem;            // s_out[224][68] = 59.5KB (reuses s_in)
    float* out_b = out + (size_t)bb * Fn * PIX + p0;
#pragma unroll
    for (int pass = 0; pass < 2; ++pass) {
        __syncthreads();                 // mainloop done / previous pass consumed
#pragma unroll
        for (int mi = 0; mi < 2; ++mi) {
            int r0 = wm0 + mi * 16 + (lane >> 2);
#pragma unroll
            for (int nj = 0; nj < 8; ++nj) {
                int nn = nj * 8 + (lane & 3) * 2;
                *(float2*)&sf[r0 * 68 + nn] =
                    make_float2(acc[mi][pass * 8 + nj][0], acc[mi][pass * 8 + nj][1]);
                *(float2*)&sf[(r0 + 8) * 68 + nn] =
                    make_float2(acc[mi][pass * 8 + nj][2], acc[mi][pass * 8 + nj][3]);
            }
        }
        __syncthreads();
        // thread tid owns pixel m=tid; 16 LDS.128 (conflict-free), 64 coalesced STG
#pragma unroll
        for (int jj = 0; jj < 16; ++jj) {
            float4 v = *(const float4*)&sf[tid * 68 + jj * 4];
            float* dst = out_b + (size_t)(pass * 64 + jj * 4) * PIX + tid;
            dst[0]               = v.x;
            dst[(size_t)PIX]     = v.y;
            dst[(size_t)2 * PIX] = v.z;
            dst[(size_t)3 * PIX] = v.w;
        }
    }
}

extern "C" void kernel_launch(void* const* d_in, const int* in_sizes, int n_in,
                              void* d_out, int out_size)
{
    (void)in_sizes; (void)n_in; (void)out_size;
    const float* in = (const float*)d_in[0];   // [32,64,112,112]
    const float* wt = (const float*)d_in[1];   // [128,64,3,3]
    float* out = (float*)d_out;                // [32,128,112,112]

    static bool attr_set = false;
    if (!attr_set) {
        cudaFuncSetAttribute(conv_hmma5_kernel,
                             cudaFuncAttributeMaxDynamicSharedMemorySize, SMEM_BYTES);
        attr_set = true;
    }
    pack_wt_h_kernel<<<(9 * BTAP + 255) / 256, 256>>>(wt);
    dim3 grid(PIX / MT, 32);                   // (56, 32) = 1792 CTAs
    conv_hmma5_kernel<<<grid, TPB, SMEM_BYTES>>>(in, out);
}